// round 5
// baseline (speedup 1.0000x reference)
#include <cuda_runtime.h>
#include <cuda_bf16.h>

// SmallVDSR: 20-layer 3x3 conv stack on [8,1,512,512] fp32.
//   conv1: 1->8 + relu
//   conv2..19: 18x (8->8 + relu)   [optimized kernel]
//   conv20: 8->1, no relu
//
// Mid-layer kernel: 32x32 tile, block (32,8), RY=4 rows/thread, all 8 oc in
// regs. Division-free staging; per-ic 6x3 input window in registers; weights
// via LDS.128 broadcast. Body fits L0 I$.

#define H 512
#define W 512
#define NB 8
#define PLANE (H * W)

__device__ float g_bufA[NB * 8 * PLANE];
__device__ float g_bufB[NB * 8 * PLANE];

// ---------------------------------------------------------------------------
// Mid layers: 8 -> 8, relu.
// ---------------------------------------------------------------------------
__global__ void __launch_bounds__(256, 3)
conv3x3_88_kernel(const float* __restrict__ in,
                  const float* __restrict__ wg,
                  float* __restrict__ out)
{
    constexpr int TX = 32, TY = 32, RY = 4;
    constexpr int SW = TX + 2;            // 34
    constexpr int SH = TY + 2;            // 34
    constexpr int STILE = SW * SH;        // 1156

    __shared__ float  s_in[8 * STILE];
    __shared__ __align__(16) float s_w[8 * 9 * 8];   // [ic][k][oc], oc contiguous

    const int tx  = threadIdx.x;          // 0..31
    const int ty  = threadIdx.y;          // 0..7
    const int tid = ty * 32 + tx;
    const int n   = blockIdx.z;
    const int gx0 = blockIdx.x * TX;
    const int gy0 = blockIdx.y * TY;

    const float* inb = in + (size_t)n * 8 * PLANE;

    // ---- stage input tile, division-free ----
    // 34x34 tile: rows covered by ty + 8*j (j=0..3) and ty+32 (ty<2);
    // cols covered by tx and 32+tx (tx<2).
    {
        const int gxA = gx0 + tx - 1;
        const bool xokA = (gxA >= 0) && (gxA < W);
        const int gxB = gx0 + 32 + tx - 1;
        const bool xokB = (tx < 2) && (gxB < W);   // gxB >= 31 always >= 0

        #pragma unroll 1
        for (int ic = 0; ic < 8; ++ic) {
            const float* src = inb + ic * PLANE;
            float* dstS = &s_in[ic * STILE];
            #pragma unroll
            for (int j = 0; j < 5; ++j) {
                int sy = ty + j * 8;
                if (j == 4 && ty >= 2) continue;     // rows 32,33 only
                int gy = gy0 + sy - 1;
                bool yok = (gy >= 0) && (gy < H);
                int rb = (gy << 9);
                float v = (yok && xokA) ? src[rb + gxA] : 0.0f;
                dstS[sy * SW + tx] = v;
                if (tx < 2) {
                    float v2 = (yok && xokB) ? src[rb + gxB] : 0.0f;
                    dstS[sy * SW + 32 + tx] = v2;
                }
            }
        }
    }

    // ---- stage + repack weights: global [oc][ic][k] -> smem [ic][k][oc] ----
    // 576 elements; divisions by constants only (cheap), done once.
    #pragma unroll 1
    for (int idx = tid; idx < 8 * 9 * 8; idx += 256) {
        int oc = idx & 7;
        int t  = idx >> 3;      // ic*9 + k
        int k  = t % 9;
        int ic = t / 9;
        s_w[idx] = wg[(oc * 8 + ic) * 9 + k];
    }

    __syncthreads();

    float acc[RY][8];
    #pragma unroll
    for (int ry = 0; ry < RY; ++ry)
        #pragma unroll
        for (int oc = 0; oc < 8; ++oc)
            acc[ry][oc] = 0.0f;

    const int y0 = ty * RY;
    const float* si0 = &s_in[y0 * SW + tx];
    const float4* wb0 = (const float4*)s_w;

    #pragma unroll 1
    for (int ic = 0; ic < 8; ++ic) {
        const float* si = si0 + ic * STILE;

        // 6x3 input window in registers (18 LDS, batched -> MLP)
        float vin[RY + 2][3];
        #pragma unroll
        for (int r = 0; r < RY + 2; ++r)
            #pragma unroll
            for (int c = 0; c < 3; ++c)
                vin[r][c] = si[r * SW + c];

        const float4* wk = wb0 + ic * 18;   // 9 k x 2 float4

        #pragma unroll
        for (int ky = 0; ky < 3; ++ky) {
            #pragma unroll
            for (int kx = 0; kx < 3; ++kx) {
                float4 wa = wk[(ky * 3 + kx) * 2 + 0];
                float4 wc = wk[(ky * 3 + kx) * 2 + 1];
                #pragma unroll
                for (int ry = 0; ry < RY; ++ry) {
                    float v = vin[ry + ky][kx];
                    acc[ry][0] = fmaf(v, wa.x, acc[ry][0]);
                    acc[ry][1] = fmaf(v, wa.y, acc[ry][1]);
                    acc[ry][2] = fmaf(v, wa.z, acc[ry][2]);
                    acc[ry][3] = fmaf(v, wa.w, acc[ry][3]);
                    acc[ry][4] = fmaf(v, wc.x, acc[ry][4]);
                    acc[ry][5] = fmaf(v, wc.y, acc[ry][5]);
                    acc[ry][6] = fmaf(v, wc.z, acc[ry][6]);
                    acc[ry][7] = fmaf(v, wc.w, acc[ry][7]);
                }
            }
        }
    }

    // ---- write out (relu) ----
    float* outb = out + (size_t)n * 8 * PLANE;
    #pragma unroll
    for (int ry = 0; ry < RY; ++ry) {
        int off = ((gy0 + y0 + ry) << 9) + gx0 + tx;
        #pragma unroll
        for (int oc = 0; oc < 8; ++oc)
            outb[oc * PLANE + off] = fmaxf(acc[ry][oc], 0.0f);
    }
}

// ---------------------------------------------------------------------------
// Generic scalar kernel (conv1: 1->8 relu, conv20: 8->1 no relu)
// ---------------------------------------------------------------------------
template <int IC, int OC, bool RELU>
__global__ void __launch_bounds__(256, 4)
conv3x3_kernel(const float* __restrict__ in,
               const float* __restrict__ wg,
               float* __restrict__ out)
{
    constexpr int TX = 32, TY = 32, RY = 4;
    constexpr int SW = TX + 2;
    constexpr int STILE = SW * (TY + 2);

    __shared__ float s_in[IC * STILE];
    __shared__ float s_w[IC * 9 * OC];

    const int tx  = threadIdx.x;
    const int ty  = threadIdx.y;
    const int tid = ty * 32 + tx;
    const int n   = blockIdx.z;
    const int gx0 = blockIdx.x * TX;
    const int gy0 = blockIdx.y * TY;

    const float* inb = in + (size_t)n * IC * PLANE;

    {
        const int gxA = gx0 + tx - 1;
        const bool xokA = (gxA >= 0) && (gxA < W);
        const int gxB = gx0 + 32 + tx - 1;
        const bool xokB = (tx < 2) && (gxB < W);

        #pragma unroll 1
        for (int ic = 0; ic < IC; ++ic) {
            const float* src = inb + ic * PLANE;
            float* dstS = &s_in[ic * STILE];
            #pragma unroll
            for (int j = 0; j < 5; ++j) {
                int sy = ty + j * 8;
                if (j == 4 && ty >= 2) continue;
                int gy = gy0 + sy - 1;
                bool yok = (gy >= 0) && (gy < H);
                int rb = (gy << 9);
                float v = (yok && xokA) ? src[rb + gxA] : 0.0f;
                dstS[sy * SW + tx] = v;
                if (tx < 2) {
                    float v2 = (yok && xokB) ? src[rb + gxB] : 0.0f;
                    dstS[sy * SW + 32 + tx] = v2;
                }
            }
        }
    }

    #pragma unroll 1
    for (int idx = tid; idx < IC * 9 * OC; idx += 256) {
        int oc = idx % OC;
        int t  = idx / OC;
        int ic = t / 9;
        int k  = t - ic * 9;
        s_w[idx] = wg[(oc * IC + ic) * 9 + k];
    }

    __syncthreads();

    float acc[RY][OC];
    #pragma unroll
    for (int ry = 0; ry < RY; ++ry)
        #pragma unroll
        for (int oc = 0; oc < OC; ++oc)
            acc[ry][oc] = 0.0f;

    const int y0 = ty * RY;
    const float* si0 = &s_in[y0 * SW + tx];

    #pragma unroll 1
    for (int ic = 0; ic < IC; ++ic) {
        const float* si = si0 + ic * STILE;

        float vin[RY + 2][3];
        #pragma unroll
        for (int r = 0; r < RY + 2; ++r)
            #pragma unroll
            for (int c = 0; c < 3; ++c)
                vin[r][c] = si[r * SW + c];

        const float* sw = &s_w[ic * 9 * OC];
        #pragma unroll
        for (int ky = 0; ky < 3; ++ky) {
            #pragma unroll
            for (int kx = 0; kx < 3; ++kx) {
                float wv[OC];
                #pragma unroll
                for (int oc = 0; oc < OC; ++oc)
                    wv[oc] = sw[(ky * 3 + kx) * OC + oc];
                #pragma unroll
                for (int ry = 0; ry < RY; ++ry) {
                    float v = vin[ry + ky][kx];
                    #pragma unroll
                    for (int oc = 0; oc < OC; ++oc)
                        acc[ry][oc] = fmaf(v, wv[oc], acc[ry][oc]);
                }
            }
        }
    }

    float* outb = out + (size_t)n * OC * PLANE;
    #pragma unroll
    for (int ry = 0; ry < RY; ++ry) {
        int off = ((gy0 + y0 + ry) << 9) + gx0 + tx;
        #pragma unroll
        for (int oc = 0; oc < OC; ++oc) {
            float v = acc[ry][oc];
            if (RELU) v = fmaxf(v, 0.0f);
            outb[oc * PLANE + off] = v;
        }
    }
}

extern "C" void kernel_launch(void* const* d_in, const int* in_sizes, int n_in,
                              void* d_out, int out_size)
{
    const float* x    = (const float*)d_in[0];  // [8,1,512,512]
    const float* w1   = (const float*)d_in[1];  // [8,1,3,3]
    const float* wmid = (const float*)d_in[2];  // [18,8,8,3,3]
    const float* w20  = (const float*)d_in[3];  // [1,8,3,3]
    float* out = (float*)d_out;                 // [8,1,512,512]

    float* bufA = nullptr;
    float* bufB = nullptr;
    cudaGetSymbolAddress((void**)&bufA, g_bufA);
    cudaGetSymbolAddress((void**)&bufB, g_bufB);

    dim3 block(32, 8);
    dim3 grid(W / 32, H / 32, NB);

    // conv1: 1 -> 8, relu
    conv3x3_kernel<1, 8, true><<<grid, block>>>(x, w1, bufA);

    // conv2..19: 18x 8 -> 8, relu
    float* src = bufA;
    float* dst = bufB;
    for (int l = 0; l < 18; ++l) {
        conv3x3_88_kernel<<<grid, block>>>(src, wmid + (size_t)l * 8 * 8 * 9, dst);
        float* t = src; src = dst; dst = t;
    }

    // conv20: 8 -> 1, no relu
    conv3x3_kernel<8, 1, false><<<grid, block>>>(src, w20, out);
}

// round 6
// speedup vs baseline: 1.1731x; 1.1731x over previous
#include <cuda_runtime.h>
#include <cuda_bf16.h>

// SmallVDSR: 20-layer 3x3 conv stack on [8,1,512,512] fp32.
//   conv1: 1->8 + relu
//   conv2..19: 18x (8->8 + relu)   [hot kernel: ~96% of runtime]
//   conv20: 8->1, no relu
//
// Hot kernel design (R5 = R2 inner loop + R4 staging, 64-reg pinned):
//   32x32 tile, block (32,8), RY=4 rows/thread, all 8 oc in regs (32 accums).
//   Division-free halo staging. Weights repacked [ic][k][oc] -> LDS.128
//   broadcasts. Inputs loaded inline per tap (keeps regs <= 64 so 4 CTAs/SM).

#define H 512
#define W 512
#define NB 8
#define PLANE (H * W)

__device__ float g_bufA[NB * 8 * PLANE];
__device__ float g_bufB[NB * 8 * PLANE];

// ---------------------------------------------------------------------------
// Mid layers: 8 -> 8, relu.
// ---------------------------------------------------------------------------
__global__ void __launch_bounds__(256, 4)
conv3x3_88_kernel(const float* __restrict__ in,
                  const float* __restrict__ wg,
                  float* __restrict__ out)
{
    constexpr int TX = 32, TY = 32, RY = 4;
    constexpr int SW = TX + 2;            // 34
    constexpr int STILE = SW * (TY + 2);  // 1156

    __shared__ float s_in[8 * STILE];
    __shared__ __align__(16) float s_w[8 * 9 * 8];   // [ic][k][oc]

    const int tx  = threadIdx.x;          // 0..31
    const int ty  = threadIdx.y;          // 0..7
    const int tid = ty * 32 + tx;
    const int n   = blockIdx.z;
    const int gx0 = blockIdx.x * TX;
    const int gy0 = blockIdx.y * TY;

    const float* inb = in + (size_t)n * 8 * PLANE;

    // ---- stage input tile, division-free (34x34 with zero halo) ----
    {
        const int gxA = gx0 + tx - 1;
        const bool xokA = (gxA >= 0) && (gxA < W);
        const int gxB = gx0 + 32 + tx - 1;
        const bool xokB = (tx < 2) && (gxB < W);

        #pragma unroll 1
        for (int ic = 0; ic < 8; ++ic) {
            const float* src = inb + ic * PLANE;
            float* dstS = &s_in[ic * STILE];
            #pragma unroll
            for (int j = 0; j < 5; ++j) {
                int sy = ty + j * 8;
                if (j == 4 && ty >= 2) continue;     // rows 32,33 only
                int gy = gy0 + sy - 1;
                bool yok = (gy >= 0) && (gy < H);
                int rb = (gy << 9);
                dstS[sy * SW + tx] = (yok && xokA) ? src[rb + gxA] : 0.0f;
                if (tx < 2)
                    dstS[sy * SW + 32 + tx] = (yok && xokB) ? src[rb + gxB] : 0.0f;
            }
        }
    }

    // ---- stage + repack weights: global [oc][ic][k] -> smem [ic][k][oc] ----
    #pragma unroll 1
    for (int idx = tid; idx < 8 * 9 * 8; idx += 256) {
        int oc = idx & 7;
        int t  = idx >> 3;      // ic*9 + k
        int k  = t % 9;
        int ic = t / 9;
        s_w[idx] = wg[(oc * 8 + ic) * 9 + k];
    }

    __syncthreads();

    float acc[RY][8];
    #pragma unroll
    for (int ry = 0; ry < RY; ++ry)
        #pragma unroll
        for (int oc = 0; oc < 8; ++oc)
            acc[ry][oc] = 0.0f;

    const int y0 = ty * RY;
    const float* si0 = &s_in[y0 * SW + tx];
    const float4* wb0 = (const float4*)s_w;

    #pragma unroll 1
    for (int ic = 0; ic < 8; ++ic) {
        const float* si = si0 + ic * STILE;
        const float4* wk = wb0 + ic * 18;     // 9 taps x 2 float4

        #pragma unroll
        for (int ky = 0; ky < 3; ++ky) {
            #pragma unroll
            for (int kx = 0; kx < 3; ++kx) {
                float4 wa = wk[(ky * 3 + kx) * 2 + 0];   // oc 0..3 (broadcast)
                float4 wc = wk[(ky * 3 + kx) * 2 + 1];   // oc 4..7
                #pragma unroll
                for (int ry = 0; ry < RY; ++ry) {
                    float v = si[(ry + ky) * SW + kx];   // inline load (regs stay low)
                    acc[ry][0] = fmaf(v, wa.x, acc[ry][0]);
                    acc[ry][1] = fmaf(v, wa.y, acc[ry][1]);
                    acc[ry][2] = fmaf(v, wa.z, acc[ry][2]);
                    acc[ry][3] = fmaf(v, wa.w, acc[ry][3]);
                    acc[ry][4] = fmaf(v, wc.x, acc[ry][4]);
                    acc[ry][5] = fmaf(v, wc.y, acc[ry][5]);
                    acc[ry][6] = fmaf(v, wc.z, acc[ry][6]);
                    acc[ry][7] = fmaf(v, wc.w, acc[ry][7]);
                }
            }
        }
    }

    // ---- write out (relu) ----
    float* outb = out + (size_t)n * 8 * PLANE;
    #pragma unroll
    for (int ry = 0; ry < RY; ++ry) {
        int off = ((gy0 + y0 + ry) << 9) + gx0 + tx;
        #pragma unroll
        for (int oc = 0; oc < 8; ++oc)
            outb[oc * PLANE + off] = fmaxf(acc[ry][oc], 0.0f);
    }
}

// ---------------------------------------------------------------------------
// Generic scalar kernel (conv1: 1->8 relu, conv20: 8->1 no relu)
// ---------------------------------------------------------------------------
template <int IC, int OC, bool RELU>
__global__ void __launch_bounds__(256, 4)
conv3x3_kernel(const float* __restrict__ in,
               const float* __restrict__ wg,
               float* __restrict__ out)
{
    constexpr int TX = 32, TY = 32, RY = 4;
    constexpr int SW = TX + 2;
    constexpr int STILE = SW * (TY + 2);

    __shared__ float s_in[IC * STILE];
    __shared__ float s_w[IC * 9 * OC];

    const int tx  = threadIdx.x;
    const int ty  = threadIdx.y;
    const int tid = ty * 32 + tx;
    const int n   = blockIdx.z;
    const int gx0 = blockIdx.x * TX;
    const int gy0 = blockIdx.y * TY;

    const float* inb = in + (size_t)n * IC * PLANE;

    {
        const int gxA = gx0 + tx - 1;
        const bool xokA = (gxA >= 0) && (gxA < W);
        const int gxB = gx0 + 32 + tx - 1;
        const bool xokB = (tx < 2) && (gxB < W);

        #pragma unroll 1
        for (int ic = 0; ic < IC; ++ic) {
            const float* src = inb + ic * PLANE;
            float* dstS = &s_in[ic * STILE];
            #pragma unroll
            for (int j = 0; j < 5; ++j) {
                int sy = ty + j * 8;
                if (j == 4 && ty >= 2) continue;
                int gy = gy0 + sy - 1;
                bool yok = (gy >= 0) && (gy < H);
                int rb = (gy << 9);
                dstS[sy * SW + tx] = (yok && xokA) ? src[rb + gxA] : 0.0f;
                if (tx < 2)
                    dstS[sy * SW + 32 + tx] = (yok && xokB) ? src[rb + gxB] : 0.0f;
            }
        }
    }

    #pragma unroll 1
    for (int idx = tid; idx < IC * 9 * OC; idx += 256) {
        int oc = idx % OC;
        int t  = idx / OC;
        int ic = t / 9;
        int k  = t - ic * 9;
        s_w[idx] = wg[(oc * IC + ic) * 9 + k];
    }

    __syncthreads();

    float acc[RY][OC];
    #pragma unroll
    for (int ry = 0; ry < RY; ++ry)
        #pragma unroll
        for (int oc = 0; oc < OC; ++oc)
            acc[ry][oc] = 0.0f;

    const int y0 = ty * RY;
    const float* si0 = &s_in[y0 * SW + tx];

    #pragma unroll 1
    for (int ic = 0; ic < IC; ++ic) {
        const float* si = si0 + ic * STILE;
        const float* sw = &s_w[ic * 9 * OC];
        #pragma unroll
        for (int ky = 0; ky < 3; ++ky) {
            #pragma unroll
            for (int kx = 0; kx < 3; ++kx) {
                float wv[OC];
                #pragma unroll
                for (int oc = 0; oc < OC; ++oc)
                    wv[oc] = sw[(ky * 3 + kx) * OC + oc];
                #pragma unroll
                for (int ry = 0; ry < RY; ++ry) {
                    float v = si[(ry + ky) * SW + kx];
                    #pragma unroll
                    for (int oc = 0; oc < OC; ++oc)
                        acc[ry][oc] = fmaf(v, wv[oc], acc[ry][oc]);
                }
            }
        }
    }

    float* outb = out + (size_t)n * OC * PLANE;
    #pragma unroll
    for (int ry = 0; ry < RY; ++ry) {
        int off = ((gy0 + y0 + ry) << 9) + gx0 + tx;
        #pragma unroll
        for (int oc = 0; oc < OC; ++oc) {
            float v = acc[ry][oc];
            if (RELU) v = fmaxf(v, 0.0f);
            outb[oc * PLANE + off] = v;
        }
    }
}

extern "C" void kernel_launch(void* const* d_in, const int* in_sizes, int n_in,
                              void* d_out, int out_size)
{
    const float* x    = (const float*)d_in[0];  // [8,1,512,512]
    const float* w1   = (const float*)d_in[1];  // [8,1,3,3]
    const float* wmid = (const float*)d_in[2];  // [18,8,8,3,3]
    const float* w20  = (const float*)d_in[3];  // [1,8,3,3]
    float* out = (float*)d_out;                 // [8,1,512,512]

    float* bufA = nullptr;
    float* bufB = nullptr;
    cudaGetSymbolAddress((void**)&bufA, g_bufA);
    cudaGetSymbolAddress((void**)&bufB, g_bufB);

    dim3 block(32, 8);
    dim3 grid(W / 32, H / 32, NB);

    // conv1: 1 -> 8, relu
    conv3x3_kernel<1, 8, true><<<grid, block>>>(x, w1, bufA);

    // conv2..19: 18x 8 -> 8, relu
    float* src = bufA;
    float* dst = bufB;
    for (int l = 0; l < 18; ++l) {
        conv3x3_88_kernel<<<grid, block>>>(src, wmid + (size_t)l * 8 * 8 * 9, dst);
        float* t = src; src = dst; dst = t;
    }

    // conv20: 8 -> 1, no relu
    conv3x3_kernel<8, 1, false><<<grid, block>>>(src, w20, out);
}

// round 7
// speedup vs baseline: 1.3261x; 1.1304x over previous
#include <cuda_runtime.h>
#include <cuda_bf16.h>

// SmallVDSR: 20-layer 3x3 conv stack on [8,1,512,512] fp32.
//   conv1: 1->8 + relu
//   conv2..19: 18x (8->8 + relu)   [hot kernel: ~96% of runtime]
//   conv20: 8->1, no relu
//
// R6 hot kernel: R2 dependence structure + R5 staging + f32x2 packed FMA.
//   32x32 tile, block (32,8), RY=4 rows/thread, 8 oc as 4 f32x2 pairs.
//   Weights in SMEM as duplicated-free u64 oc-pairs [ic][tap][pair];
//   loaded per tap (4x LDS.64 broadcast) -- NO per-ky hoist arrays.
//   Inputs loaded inline per (ry,tap), duplicated via mov.b64 (alu pipe).
//   __launch_bounds__(256,4) pins <=64 regs -> 4 CTAs/SM.

#define H 512
#define W 512
#define NB 8
#define PLANE (H * W)

typedef unsigned long long u64;

__device__ float g_bufA[NB * 8 * PLANE];
__device__ float g_bufB[NB * 8 * PLANE];

__device__ __forceinline__ u64 pack_dup(float v) {
    u64 r;
    asm("mov.b64 %0, {%1, %1};" : "=l"(r) : "f"(v));
    return r;
}
__device__ __forceinline__ void fma2(u64& acc, u64 a, u64 b) {
    asm("fma.rn.f32x2 %0, %1, %2, %0;" : "+l"(acc) : "l"(a), "l"(b));
}
__device__ __forceinline__ void unpack2(float& lo, float& hi, u64 v) {
    asm("mov.b64 {%0, %1}, %2;" : "=f"(lo), "=f"(hi) : "l"(v));
}
__device__ __forceinline__ u64 pack2(float lo, float hi) {
    u64 r;
    asm("mov.b64 %0, {%1, %2};" : "=l"(r) : "f"(lo), "f"(hi));
    return r;
}

// ---------------------------------------------------------------------------
// Mid layers: 8 -> 8, relu. Packed f32x2 over oc-pairs, occ-4 pinned.
// ---------------------------------------------------------------------------
__global__ void __launch_bounds__(256, 4)
conv3x3_88_kernel(const float* __restrict__ in,
                  const float* __restrict__ wg,
                  float* __restrict__ out)
{
    constexpr int TX = 32, TY = 32, RY = 4;
    constexpr int SW = TX + 2;            // 34
    constexpr int STILE = SW * (TY + 2);  // 1156

    __shared__ float s_in[8 * STILE];
    __shared__ __align__(16) u64 s_w[8 * 9 * 4];  // [ic][tap][pair]

    const int tx  = threadIdx.x;          // 0..31
    const int ty  = threadIdx.y;          // 0..7
    const int tid = ty * 32 + tx;
    const int n   = blockIdx.z;
    const int gx0 = blockIdx.x * TX;
    const int gy0 = blockIdx.y * TY;

    const float* inb = in + (size_t)n * 8 * PLANE;

    // ---- stage input tile, division-free (34x34 with zero halo) ----
    {
        const int gxA = gx0 + tx - 1;
        const bool xokA = (gxA >= 0) && (gxA < W);
        const int gxB = gx0 + 32 + tx - 1;
        const bool xokB = (tx < 2) && (gxB < W);

        #pragma unroll 1
        for (int ic = 0; ic < 8; ++ic) {
            const float* src = inb + ic * PLANE;
            float* dstS = &s_in[ic * STILE];
            #pragma unroll
            for (int j = 0; j < 5; ++j) {
                int sy = ty + j * 8;
                if (j == 4 && ty >= 2) continue;     // rows 32,33 only
                int gy = gy0 + sy - 1;
                bool yok = (gy >= 0) && (gy < H);
                int rb = (gy << 9);
                dstS[sy * SW + tx] = (yok && xokA) ? src[rb + gxA] : 0.0f;
                if (tx < 2)
                    dstS[sy * SW + 32 + tx] = (yok && xokB) ? src[rb + gxB] : 0.0f;
            }
        }
    }

    // ---- stage + repack weights: global [oc][ic][k] -> smem u64 [ic][k][p] ----
    #pragma unroll 1
    for (int idx = tid; idx < 8 * 9 * 4; idx += 256) {
        int p  = idx & 3;
        int t  = idx >> 2;      // ic*9 + k
        int k  = t % 9;
        int ic = t / 9;
        float lo = wg[((2 * p + 0) * 8 + ic) * 9 + k];
        float hi = wg[((2 * p + 1) * 8 + ic) * 9 + k];
        s_w[idx] = pack2(lo, hi);
    }

    __syncthreads();

    u64 acc[RY][4];
    #pragma unroll
    for (int ry = 0; ry < RY; ++ry)
        #pragma unroll
        for (int p = 0; p < 4; ++p)
            acc[ry][p] = 0ull;

    const int y0 = ty * RY;
    const float* si0 = &s_in[y0 * SW + tx];

    #pragma unroll 1
    for (int ic = 0; ic < 8; ++ic) {
        const float* si = si0 + ic * STILE;
        const u64* wk = &s_w[ic * 36];

        #pragma unroll
        for (int t = 0; t < 9; ++t) {       // tap = ky*3+kx (compile-time)
            const int ky = t / 3;
            const int kx = t % 3;
            // 4 oc-pair weights for this tap (LDS.64 broadcast, used 4x each)
            u64 w0 = wk[t * 4 + 0];
            u64 w1 = wk[t * 4 + 1];
            u64 w2 = wk[t * 4 + 2];
            u64 w3 = wk[t * 4 + 3];
            #pragma unroll
            for (int ry = 0; ry < RY; ++ry) {
                float v = si[(ry + ky) * SW + kx];   // inline load
                u64 vv = pack_dup(v);                // alu-pipe mov
                fma2(acc[ry][0], vv, w0);
                fma2(acc[ry][1], vv, w1);
                fma2(acc[ry][2], vv, w2);
                fma2(acc[ry][3], vv, w3);
            }
        }
    }

    // ---- write out (relu) ----
    float* outb = out + (size_t)n * 8 * PLANE;
    #pragma unroll
    for (int ry = 0; ry < RY; ++ry) {
        int off = ((gy0 + y0 + ry) << 9) + gx0 + tx;
        #pragma unroll
        for (int p = 0; p < 4; ++p) {
            float lo, hi;
            unpack2(lo, hi, acc[ry][p]);
            outb[(2 * p + 0) * PLANE + off] = fmaxf(lo, 0.0f);
            outb[(2 * p + 1) * PLANE + off] = fmaxf(hi, 0.0f);
        }
    }
}

// ---------------------------------------------------------------------------
// Generic scalar kernel (conv1: 1->8 relu, conv20: 8->1 no relu)
// ---------------------------------------------------------------------------
template <int IC, int OC, bool RELU>
__global__ void __launch_bounds__(256, 4)
conv3x3_kernel(const float* __restrict__ in,
               const float* __restrict__ wg,
               float* __restrict__ out)
{
    constexpr int TX = 32, TY = 32, RY = 4;
    constexpr int SW = TX + 2;
    constexpr int STILE = SW * (TY + 2);

    __shared__ float s_in[IC * STILE];
    __shared__ float s_w[IC * 9 * OC];

    const int tx  = threadIdx.x;
    const int ty  = threadIdx.y;
    const int tid = ty * 32 + tx;
    const int n   = blockIdx.z;
    const int gx0 = blockIdx.x * TX;
    const int gy0 = blockIdx.y * TY;

    const float* inb = in + (size_t)n * IC * PLANE;

    {
        const int gxA = gx0 + tx - 1;
        const bool xokA = (gxA >= 0) && (gxA < W);
        const int gxB = gx0 + 32 + tx - 1;
        const bool xokB = (tx < 2) && (gxB < W);

        #pragma unroll 1
        for (int ic = 0; ic < IC; ++ic) {
            const float* src = inb + ic * PLANE;
            float* dstS = &s_in[ic * STILE];
            #pragma unroll
            for (int j = 0; j < 5; ++j) {
                int sy = ty + j * 8;
                if (j == 4 && ty >= 2) continue;
                int gy = gy0 + sy - 1;
                bool yok = (gy >= 0) && (gy < H);
                int rb = (gy << 9);
                dstS[sy * SW + tx] = (yok && xokA) ? src[rb + gxA] : 0.0f;
                if (tx < 2)
                    dstS[sy * SW + 32 + tx] = (yok && xokB) ? src[rb + gxB] : 0.0f;
            }
        }
    }

    #pragma unroll 1
    for (int idx = tid; idx < IC * 9 * OC; idx += 256) {
        int oc = idx % OC;
        int t  = idx / OC;
        int ic = t / 9;
        int k  = t - ic * 9;
        s_w[idx] = wg[(oc * IC + ic) * 9 + k];
    }

    __syncthreads();

    float acc[RY][OC];
    #pragma unroll
    for (int ry = 0; ry < RY; ++ry)
        #pragma unroll
        for (int oc = 0; oc < OC; ++oc)
            acc[ry][oc] = 0.0f;

    const int y0 = ty * RY;
    const float* si0 = &s_in[y0 * SW + tx];

    #pragma unroll 1
    for (int ic = 0; ic < IC; ++ic) {
        const float* si = si0 + ic * STILE;
        const float* sw = &s_w[ic * 9 * OC];
        #pragma unroll
        for (int ky = 0; ky < 3; ++ky) {
            #pragma unroll
            for (int kx = 0; kx < 3; ++kx) {
                float wv[OC];
                #pragma unroll
                for (int oc = 0; oc < OC; ++oc)
                    wv[oc] = sw[(ky * 3 + kx) * OC + oc];
                #pragma unroll
                for (int ry = 0; ry < RY; ++ry) {
                    float v = si[(ry + ky) * SW + kx];
                    #pragma unroll
                    for (int oc = 0; oc < OC; ++oc)
                        acc[ry][oc] = fmaf(v, wv[oc], acc[ry][oc]);
                }
            }
        }
    }

    float* outb = out + (size_t)n * OC * PLANE;
    #pragma unroll
    for (int ry = 0; ry < RY; ++ry) {
        int off = ((gy0 + y0 + ry) << 9) + gx0 + tx;
        #pragma unroll
        for (int oc = 0; oc < OC; ++oc) {
            float v = acc[ry][oc];
            if (RELU) v = fmaxf(v, 0.0f);
            outb[oc * PLANE + off] = v;
        }
    }
}

extern "C" void kernel_launch(void* const* d_in, const int* in_sizes, int n_in,
                              void* d_out, int out_size)
{
    const float* x    = (const float*)d_in[0];  // [8,1,512,512]
    const float* w1   = (const float*)d_in[1];  // [8,1,3,3]
    const float* wmid = (const float*)d_in[2];  // [18,8,8,3,3]
    const float* w20  = (const float*)d_in[3];  // [1,8,3,3]
    float* out = (float*)d_out;                 // [8,1,512,512]

    float* bufA = nullptr;
    float* bufB = nullptr;
    cudaGetSymbolAddress((void**)&bufA, g_bufA);
    cudaGetSymbolAddress((void**)&bufB, g_bufB);

    dim3 block(32, 8);
    dim3 grid(W / 32, H / 32, NB);

    // conv1: 1 -> 8, relu
    conv3x3_kernel<1, 8, true><<<grid, block>>>(x, w1, bufA);

    // conv2..19: 18x 8 -> 8, relu
    float* src = bufA;
    float* dst = bufB;
    for (int l = 0; l < 18; ++l) {
        conv3x3_88_kernel<<<grid, block>>>(src, wmid + (size_t)l * 8 * 8 * 9, dst);
        float* t = src; src = dst; dst = t;
    }

    // conv20: 8 -> 1, no relu
    conv3x3_kernel<8, 1, false><<<grid, block>>>(src, w20, out);
}

// round 8
// speedup vs baseline: 1.4132x; 1.0657x over previous
#include <cuda_runtime.h>
#include <cuda_bf16.h>

// SmallVDSR: 20-layer 3x3 conv stack on [8,1,512,512] fp32.
//   conv1: 1->8 + relu
//   conv2..19: 18x (8->8 + relu)   [hot kernel: ~96% of runtime]
//   conv20: 8->1, no relu
//
// R7: weights moved OFF the smem crossbar into the constant bank.
//   - repack kernel writes wmid -> g_wpack as [l][ic][tap][oc]
//   - cudaMemcpyAsync D2D g_wpack -> __constant__ c_w (41.5 KB, capturable)
//   - mid kernel reads weights via uniform const-bank addressing (ULDC/UR),
//     smem holds ONLY the input tile (36 crossbar cyc/ic instead of 108).

#define H 512
#define W 512
#define NB 8
#define PLANE (H * W)

__device__ float g_bufA[NB * 8 * PLANE];
__device__ float g_bufB[NB * 8 * PLANE];

// Mid-layer weights, repacked [l][ic][tap][oc] (oc contiguous): 18*8*9*8 floats.
__constant__ float c_w[18 * 8 * 9 * 8];
__device__   float g_wpack[18 * 8 * 9 * 8];

__global__ void repack_weights_kernel(const float* __restrict__ wmid)
{
    int idx = blockIdx.x * blockDim.x + threadIdx.x;   // [l][ic][t][oc]
    if (idx >= 18 * 8 * 9 * 8) return;
    int oc = idx & 7;
    int t  = (idx >> 3) % 9;
    int ic = ((idx >> 3) / 9) & 7;
    int l  = idx / 576;
    // source layout: [l][oc][ic][ky][kx]
    g_wpack[idx] = wmid[l * 576 + (oc * 8 + ic) * 9 + t];
}

// ---------------------------------------------------------------------------
// Mid layers: 8 -> 8, relu. Weights from constant bank (uniform datapath).
// 32x32 tile, block (32,8), RY=4 rows/thread, 8 oc accumulators.
// ---------------------------------------------------------------------------
__global__ void __launch_bounds__(256, 4)
conv3x3_88_kernel(const float* __restrict__ in,
                  float* __restrict__ out,
                  int lbase)                 // = layer * 576
{
    constexpr int TX = 32, TY = 32, RY = 4;
    constexpr int SW = TX + 2;            // 34
    constexpr int STILE = SW * (TY + 2);  // 1156

    __shared__ float s_in[8 * STILE];

    const int tx  = threadIdx.x;          // 0..31
    const int ty  = threadIdx.y;          // 0..7
    const int n   = blockIdx.z;
    const int gx0 = blockIdx.x * TX;
    const int gy0 = blockIdx.y * TY;

    const float* inb = in + (size_t)n * 8 * PLANE;

    // ---- stage input tile, division-free (34x34 with zero halo) ----
    {
        const int gxA = gx0 + tx - 1;
        const bool xokA = (gxA >= 0) && (gxA < W);
        const int gxB = gx0 + 32 + tx - 1;
        const bool xokB = (tx < 2) && (gxB < W);

        #pragma unroll 1
        for (int ic = 0; ic < 8; ++ic) {
            const float* src = inb + ic * PLANE;
            float* dstS = &s_in[ic * STILE];
            #pragma unroll
            for (int j = 0; j < 5; ++j) {
                int sy = ty + j * 8;
                if (j == 4 && ty >= 2) continue;     // rows 32,33 only
                int gy = gy0 + sy - 1;
                bool yok = (gy >= 0) && (gy < H);
                int rb = (gy << 9);
                dstS[sy * SW + tx] = (yok && xokA) ? src[rb + gxA] : 0.0f;
                if (tx < 2)
                    dstS[sy * SW + 32 + tx] = (yok && xokB) ? src[rb + gxB] : 0.0f;
            }
        }
    }

    __syncthreads();

    float acc[RY][8];
    #pragma unroll
    for (int ry = 0; ry < RY; ++ry)
        #pragma unroll
        for (int oc = 0; oc < 8; ++oc)
            acc[ry][oc] = 0.0f;

    const int y0 = ty * RY;
    const float* si0 = &s_in[y0 * SW + tx];

    #pragma unroll 1
    for (int ic = 0; ic < 8; ++ic) {
        const float* si = si0 + ic * STILE;
        const int wbase = lbase + ic * 72;    // uniform across block

        #pragma unroll
        for (int ky = 0; ky < 3; ++ky) {
            #pragma unroll
            for (int kx = 0; kx < 3; ++kx) {
                const int tb = wbase + (ky * 3 + kx) * 8;
                // uniform const-bank loads (candidate ULDC -> UR operands)
                float w0 = c_w[tb + 0];
                float w1 = c_w[tb + 1];
                float w2 = c_w[tb + 2];
                float w3 = c_w[tb + 3];
                float w4 = c_w[tb + 4];
                float w5 = c_w[tb + 5];
                float w6 = c_w[tb + 6];
                float w7 = c_w[tb + 7];
                #pragma unroll
                for (int ry = 0; ry < RY; ++ry) {
                    float v = si[(ry + ky) * SW + kx];   // only crossbar traffic
                    acc[ry][0] = fmaf(v, w0, acc[ry][0]);
                    acc[ry][1] = fmaf(v, w1, acc[ry][1]);
                    acc[ry][2] = fmaf(v, w2, acc[ry][2]);
                    acc[ry][3] = fmaf(v, w3, acc[ry][3]);
                    acc[ry][4] = fmaf(v, w4, acc[ry][4]);
                    acc[ry][5] = fmaf(v, w5, acc[ry][5]);
                    acc[ry][6] = fmaf(v, w6, acc[ry][6]);
                    acc[ry][7] = fmaf(v, w7, acc[ry][7]);
                }
            }
        }
    }

    // ---- write out (relu) ----
    float* outb = out + (size_t)n * 8 * PLANE;
    #pragma unroll
    for (int ry = 0; ry < RY; ++ry) {
        int off = ((gy0 + y0 + ry) << 9) + gx0 + tx;
        #pragma unroll
        for (int oc = 0; oc < 8; ++oc)
            outb[oc * PLANE + off] = fmaxf(acc[ry][oc], 0.0f);
    }
}

// ---------------------------------------------------------------------------
// Generic scalar kernel (conv1: 1->8 relu, conv20: 8->1 no relu)
// ---------------------------------------------------------------------------
template <int IC, int OC, bool RELU>
__global__ void __launch_bounds__(256, 4)
conv3x3_kernel(const float* __restrict__ in,
               const float* __restrict__ wg,
               float* __restrict__ out)
{
    constexpr int TX = 32, TY = 32, RY = 4;
    constexpr int SW = TX + 2;
    constexpr int STILE = SW * (TY + 2);

    __shared__ float s_in[IC * STILE];
    __shared__ float s_w[IC * 9 * OC];

    const int tx  = threadIdx.x;
    const int ty  = threadIdx.y;
    const int tid = ty * 32 + tx;
    const int n   = blockIdx.z;
    const int gx0 = blockIdx.x * TX;
    const int gy0 = blockIdx.y * TY;

    const float* inb = in + (size_t)n * IC * PLANE;

    {
        const int gxA = gx0 + tx - 1;
        const bool xokA = (gxA >= 0) && (gxA < W);
        const int gxB = gx0 + 32 + tx - 1;
        const bool xokB = (tx < 2) && (gxB < W);

        #pragma unroll 1
        for (int ic = 0; ic < IC; ++ic) {
            const float* src = inb + ic * PLANE;
            float* dstS = &s_in[ic * STILE];
            #pragma unroll
            for (int j = 0; j < 5; ++j) {
                int sy = ty + j * 8;
                if (j == 4 && ty >= 2) continue;
                int gy = gy0 + sy - 1;
                bool yok = (gy >= 0) && (gy < H);
                int rb = (gy << 9);
                dstS[sy * SW + tx] = (yok && xokA) ? src[rb + gxA] : 0.0f;
                if (tx < 2)
                    dstS[sy * SW + 32 + tx] = (yok && xokB) ? src[rb + gxB] : 0.0f;
            }
        }
    }

    #pragma unroll 1
    for (int idx = tid; idx < IC * 9 * OC; idx += 256) {
        int oc = idx % OC;
        int t  = idx / OC;
        int ic = t / 9;
        int k  = t - ic * 9;
        s_w[idx] = wg[(oc * IC + ic) * 9 + k];
    }

    __syncthreads();

    float acc[RY][OC];
    #pragma unroll
    for (int ry = 0; ry < RY; ++ry)
        #pragma unroll
        for (int oc = 0; oc < OC; ++oc)
            acc[ry][oc] = 0.0f;

    const int y0 = ty * RY;
    const float* si0 = &s_in[y0 * SW + tx];

    #pragma unroll 1
    for (int ic = 0; ic < IC; ++ic) {
        const float* si = si0 + ic * STILE;
        const float* sw = &s_w[ic * 9 * OC];
        #pragma unroll
        for (int ky = 0; ky < 3; ++ky) {
            #pragma unroll
            for (int kx = 0; kx < 3; ++kx) {
                float wv[OC];
                #pragma unroll
                for (int oc = 0; oc < OC; ++oc)
                    wv[oc] = sw[(ky * 3 + kx) * OC + oc];
                #pragma unroll
                for (int ry = 0; ry < RY; ++ry) {
                    float v = si[(ry + ky) * SW + kx];
                    #pragma unroll
                    for (int oc = 0; oc < OC; ++oc)
                        acc[ry][oc] = fmaf(v, wv[oc], acc[ry][oc]);
                }
            }
        }
    }

    float* outb = out + (size_t)n * OC * PLANE;
    #pragma unroll
    for (int ry = 0; ry < RY; ++ry) {
        int off = ((gy0 + y0 + ry) << 9) + gx0 + tx;
        #pragma unroll
        for (int oc = 0; oc < OC; ++oc) {
            float v = acc[ry][oc];
            if (RELU) v = fmaxf(v, 0.0f);
            outb[oc * PLANE + off] = v;
        }
    }
}

extern "C" void kernel_launch(void* const* d_in, const int* in_sizes, int n_in,
                              void* d_out, int out_size)
{
    const float* x    = (const float*)d_in[0];  // [8,1,512,512]
    const float* w1   = (const float*)d_in[1];  // [8,1,3,3]
    const float* wmid = (const float*)d_in[2];  // [18,8,8,3,3]
    const float* w20  = (const float*)d_in[3];  // [1,8,3,3]
    float* out = (float*)d_out;                 // [8,1,512,512]

    float* bufA = nullptr;
    float* bufB = nullptr;
    float* wpack = nullptr;
    cudaGetSymbolAddress((void**)&bufA, g_bufA);
    cudaGetSymbolAddress((void**)&bufB, g_bufB);
    cudaGetSymbolAddress((void**)&wpack, g_wpack);

    // repack mid weights and stage them into the constant bank (capturable)
    repack_weights_kernel<<<(18 * 8 * 9 * 8 + 255) / 256, 256>>>(wmid);
    cudaMemcpyToSymbolAsync(c_w, wpack, 18 * 8 * 9 * 8 * sizeof(float), 0,
                            cudaMemcpyDeviceToDevice, 0);

    dim3 block(32, 8);
    dim3 grid(W / 32, H / 32, NB);

    // conv1: 1 -> 8, relu
    conv3x3_kernel<1, 8, true><<<grid, block>>>(x, w1, bufA);

    // conv2..19: 18x 8 -> 8, relu (constant-bank weights)
    float* src = bufA;
    float* dst = bufB;
    for (int l = 0; l < 18; ++l) {
        conv3x3_88_kernel<<<grid, block>>>(src, dst, l * 576);
        float* t = src; src = dst; dst = t;
    }

    // conv20: 8 -> 1, no relu
    conv3x3_kernel<8, 1, false><<<grid, block>>>(src, w20, out);
}